// round 9
// baseline (speedup 1.0000x reference)
#include <cuda_runtime.h>
#include <cstdint>

#define NF      26
#define VOCAB   100000
#define EMBED   16
#define BATCH   16384
#define KDIM    16
#define NTOT    (NF * EMBED)   // 416
#define VSTRIDE 20             // [v0..v15, W, s2, pad, pad] -> conflict-free float4 LDS
#define THREADS 128

// ---- packed f32x2 helpers (FFMA2/FMUL2 only reachable via PTX) ----
__device__ __forceinline__ uint64_t pack2(float lo, float hi) {
    uint64_t r;
    asm("mov.b64 %0, {%1, %2};" : "=l"(r) : "f"(lo), "f"(hi));
    return r;
}
__device__ __forceinline__ void fma2(uint64_t& d, uint64_t a, uint64_t b) {
    asm("fma.rn.f32x2 %0, %1, %2, %0;" : "+l"(d) : "l"(a), "l"(b));
}
__device__ __forceinline__ uint64_t mul2(uint64_t a, uint64_t b) {
    uint64_t r;
    asm("mul.rn.f32x2 %0, %1, %2;" : "=l"(r) : "l"(a), "l"(b));
    return r;
}
__device__ __forceinline__ void unpack2(uint64_t p, float& lo, float& hi) {
    asm("mov.b64 {%0, %1}, %2;" : "=f"(lo), "=f"(hi) : "l"(p));
}

extern __shared__ float smem[];

__global__ __launch_bounds__(THREADS)
void fm_kernel(const int* __restrict__ X,
               const float* __restrict__ tables,
               const float* __restrict__ W,
               const float* __restrict__ bptr,
               const float* __restrict__ v,
               float* __restrict__ out)
{
    float* v_sh = smem;                      // [NTOT][VSTRIDE]

    const int tid = threadIdx.x;

    // Stage augmented tile: row n = [v[n][0..15], W[n], s2[n], 0, 0]
    for (int n = tid; n < NTOT; n += THREADS) {
        const float4* vr = (const float4*)(v + n * KDIM);
        float s2 = 0.f;
#pragma unroll
        for (int q = 0; q < 4; q++) {
            float4 a = vr[q];
            ((float4*)(v_sh + n * VSTRIDE))[q] = a;
            s2 += a.x * a.x + a.y * a.y + a.z * a.z + a.w * a.w;
        }
        v_sh[n * VSTRIDE + 16] = __ldg(&W[n]);
        v_sh[n * VSTRIDE + 17] = s2;
        v_sh[n * VSTRIDE + 18] = 0.f;
        v_sh[n * VSTRIDE + 19] = 0.f;
    }

    const int lane = tid & 31;
    const int j    = lane & 15;              // embedding component owned by this lane
    const int warp = tid >> 5;
    // Warp covers 4 rows: lanes 0-15 -> rows r0,r0+1 ; lanes 16-31 -> r0+2,r0+3.
    const int row0 = blockIdx.x * 16 + warp * 4 + (lane >> 4) * 2;
    const int row1 = row0 + 1;
    const float bval = __ldg(bptr);

    __syncthreads();

    // Packed accumulators: xv0p[p] = {xv0[2p], xv0[2p+1]} etc.
    uint64_t xv0p[8], xv1p[8];
#pragma unroll
    for (int p = 0; p < 8; p++) { xv0p[p] = 0ull; xv1p[p] = 0ull; }
    uint64_t linp = 0ull;                    // {lin_row0, lin_row1}
    uint64_t ssp  = 0ull;                    // {ss_row0,  ss_row1}

    const int* xrow0 = X + row0 * NF;
    const int* xrow1 = X + row1 * NF;

#pragma unroll
    for (int f = 0; f < NF; f++) {
        int idx0 = __ldg(&xrow0[f]);         // uniform across half-warp -> broadcast
        int idx1 = __ldg(&xrow1[f]);
        const float* base = tables + (long long)f * VOCAB * EMBED;
        float e0 = __ldg(base + (long long)idx0 * EMBED + j);  // half-warp covers 64B line
        float e1 = __ldg(base + (long long)idx1 * EMBED + j);

        uint64_t e0p = pack2(e0, e0);
        uint64_t e1p = pack2(e1, e1);
        uint64_t e01 = pack2(e0, e1);
        uint64_t e2  = mul2(e01, e01);       // {e0^2, e1^2}

        const float* rbase = v_sh + (f * EMBED + j) * VSTRIDE;
        const ulonglong2* vr = (const ulonglong2*)rbase;
#pragma unroll
        for (int q = 0; q < 4; q++) {
            ulonglong2 a = vr[q];            // two packed f32 pairs
            fma2(xv0p[2 * q + 0], e0p, a.x);
            fma2(xv0p[2 * q + 1], e0p, a.y);
            fma2(xv1p[2 * q + 0], e1p, a.x);
            fma2(xv1p[2 * q + 1], e1p, a.y);
        }
        float4 ws = ((const float4*)rbase)[4];   // .x = W[n], .y = s2[n]
        fma2(linp, e01, pack2(ws.x, ws.x));
        fma2(ssp,  e2,  pack2(ws.y, ws.y));
    }

    // Unpack xv partials: a0[k] = this lane's partial of xv_row0[k] (over its j only).
    float a0[KDIM], a1[KDIM];
#pragma unroll
    for (int p = 0; p < 8; p++) {
        unpack2(xv0p[p], a0[2 * p], a0[2 * p + 1]);
        unpack2(xv1p[p], a1[2 * p], a1[2 * p + 1]);
    }

    // Transpose-reduce across the 16-lane half: after 4 levels, a0[0] holds the
    // FULL sum over all j of xv[k] for k == this lane's j. 15 shfl per row.
    // (XOR offsets <= 8 stay inside the half-warp.)
#pragma unroll
    for (int off = 8; off >= 1; off >>= 1) {
#pragma unroll
        for (int i = 0; i < off; i++) {
            const int keep = (j & off) ? i + off : i;
            const int send = (j & off) ? i : i + off;
            float u0 = __shfl_xor_sync(0xffffffffu, a0[send], off);
            float u1 = __shfl_xor_sync(0xffffffffu, a1[send], off);
            a0[i] = a0[keep] + u0;
            a1[i] = a1[keep] + u1;
        }
    }

    // Per-lane scalar contribution: 0.5*xv_k^2 (k=j term) + lin_partial - 0.5*ss_partial.
    float lin0, lin1, s0, s1;
    unpack2(linp, lin0, lin1);
    unpack2(ssp,  s0,  s1);
    float c0 = fmaf(0.5f * a0[0], a0[0], fmaf(-0.5f, s0, lin0));
    float c1 = fmaf(0.5f * a1[0], a1[0], fmaf(-0.5f, s1, lin1));

    // Final scalar butterfly over the half-warp.
#pragma unroll
    for (int off = 8; off >= 1; off >>= 1) {
        c0 += __shfl_xor_sync(0xffffffffu, c0, off);
        c1 += __shfl_xor_sync(0xffffffffu, c1, off);
    }

    if (j == 0) {
        float z0 = c0 + bval;
        float z1 = c1 + bval;
        out[row0] = 1.f / (1.f + __expf(-z0));
        out[row1] = 1.f / (1.f + __expf(-z1));
    }
}

extern "C" void kernel_launch(void* const* d_in, const int* in_sizes, int n_in,
                              void* d_out, int out_size)
{
    const int*   X      = (const int*)d_in[0];
    const float* tables = (const float*)d_in[1];
    const float* W      = (const float*)d_in[2];
    const float* b      = (const float*)d_in[3];
    const float* v      = (const float*)d_in[4];
    float*       out    = (float*)d_out;

    const size_t shmem = (size_t)NTOT * VSTRIDE * sizeof(float);   // 33280 B
    cudaFuncSetAttribute(fm_kernel, cudaFuncAttributeMaxDynamicSharedMemorySize,
                         (int)shmem);

    // 16 rows per block (4 warps x 4 rows), 1024 blocks covers BATCH=16384.
    fm_kernel<<<BATCH / 16, THREADS, shmem>>>(X, tables, W, b, v, out);
}